// round 13
// baseline (speedup 1.0000x reference)
#include <cuda_runtime.h>

#define WIDTH   512
#define HEIGHT  512
#define TH      8                  // output rows per CTA
#define NTH     256                // threads per CTA
// 65 groups of 8 tuples x 16B: groups 0..63 = pixels (XOR-swizzled),
// group 64 = pre-reflected x-halos (k=0..2: x=510,509,508; k=5..7: x=3,2,1)
#define ROWB    (65 * 128)         // 8320 bytes per SMEM row
#define SMEM_BYTES (TH * ROWB)     // 66560

typedef unsigned long long u64;

// reflect padding (pad=3 < dim, single reflection suffices)
__device__ __forceinline__ int refl(int i, int n) {
    i = i < 0 ? -i : i;
    return i >= n ? 2 * n - 2 - i : i;
}

// XOR swizzle: byte offset of tuple #x within a vb row (groups 0..63).
__device__ __forceinline__ unsigned vboff(int x) {
    return (unsigned)((x ^ ((x >> 3) & 7)) << 4);
}

__device__ __forceinline__ u64 pack2(float lo, float hi) {
    u64 r; asm("mov.b64 %0, {%1, %2};" : "=l"(r) : "f"(lo), "f"(hi)); return r;
}
__device__ __forceinline__ void unpack2(u64 v, float& lo, float& hi) {
    asm("mov.b64 {%0, %1}, %2;" : "=f"(lo), "=f"(hi) : "l"(v));
}
// packed dual FMA -> FFMA2 in SASS (PTX-only form)
__device__ __forceinline__ u64 fma2(u64 a, u64 b, u64 c) {
    u64 d; asm("fma.rn.f32x2 %0, %1, %2, %3;" : "=l"(d) : "l"(a), "l"(b), "l"(c));
    return d;
}
__device__ __forceinline__ float frsq_ap(float x) {
    float r; asm("rsqrt.approx.f32 %0, %1;" : "=f"(r) : "f"(x)); return r;
}

// Stage-1 vertical blur for one column (R9-identical memory schedule), plus
// predicated duplicate STS into the halo group for the 6 boundary columns.
template<bool EDGE>
__device__ __forceinline__ void stage1_col(const float* __restrict__ cp,
                                           const float* __restrict__ sp,
                                           unsigned char* sm,
                                           int x, int y0, const u64* G2) {
    const unsigned sb = vboff(x);
    int hs = -1;                               // halo duplicate byte in group 64
    if (x >= 1 && x <= 3)      hs = 8192 + 16 * (8 - x);     // k = 7,6,5
    if (x >= 508 && x <= 510)  hs = 8192 + 16 * (510 - x);   // k = 0,1,2

    u64 rc[7], rs[7];                          // ring: packed (v, v^2)
    const float* cr = cp + (y0 - 3) * WIDTH + x;   // valid base when !EDGE
    const float* sr = sp + (y0 - 3) * WIDTH + x;
    #pragma unroll
    for (int i = 0; i < TH + 6; ++i) {
        float c, s;
        if (EDGE) {
            const int gy = refl(y0 - 3 + i, HEIGHT);
            c = __ldg(cp + gy * WIDTH + x);
            s = __ldg(sp + gy * WIDTH + x);
        } else {
            c = __ldg(cr + i * WIDTH);         // LDG [R + imm]
            s = __ldg(sr + i * WIDTH);
        }
        rc[i % 7] = pack2(c, c * c);
        rs[i % 7] = pack2(s, s * s);
        if (i >= 6) {
            const int o = i - 6;               // output row within tile
            u64 a = 0ull, d = 0ull;            // (mean, E2) packed per tensor
            #pragma unroll
            for (int k = 0; k < 7; ++k) {
                const int q = (o + k) % 7;     // compile-time after unroll
                a = fma2(G2[k], rc[q], a);
                d = fma2(G2[k], rs[q], d);
            }
            ulonglong2 v; v.x = a; v.y = d;
            *reinterpret_cast<ulonglong2*>(sm + o * ROWB + sb) = v;
            if (hs >= 0)
                *reinterpret_cast<ulonglong2*>(sm + o * ROWB + hs) = v;
        }
    }
}

__global__ __launch_bounds__(NTH, 3)
void adain_local_kernel(const float* __restrict__ content,
                        const float* __restrict__ style,
                        float* __restrict__ out) {
    extern __shared__ unsigned char sm[];

    const float G[7] = {0.0044330481752437f, 0.0540055826224143f,
                        0.2420362293761143f, 0.3990502746173879f,
                        0.2420362293761143f, 0.0540055826224143f,
                        0.0044330481752437f};
    u64 G2[7];
    #pragma unroll
    for (int k = 0; k < 7; ++k) G2[k] = pack2(G[k], G[k]);

    const int plane = blockIdx.y;
    const int y0    = blockIdx.x * TH;
    const size_t pb = (size_t)plane * (WIDTH * HEIGHT);
    const float* cp = content + pb;
    const float* sp = style   + pb;
    float*       op = out     + pb;
    const int tid = threadIdx.x;

    // -------- Stage 1: vertical 7-tap blur; each thread handles 2 columns ---
    if (y0 >= 3 && y0 + TH + 3 <= HEIGHT) {
        stage1_col<false>(cp, sp, sm, tid,       y0, G2);
        stage1_col<false>(cp, sp, sm, tid + NTH, y0, G2);
    } else {
        stage1_col<true >(cp, sp, sm, tid,       y0, G2);
        stage1_col<true >(cp, sp, sm, tid + NTH, y0, G2);
    }
    __syncthreads();

    // ---- Stage 2: horizontal 7-tap + AdaIN epilogue -------------------------
    // Same loads / FMA order as R9, but addresses via 3 group bases + XOR
    // masks (2 ALU/load) and pre-reflected halo group (no refl, no branches).
    #pragma unroll
    for (int t = 0; t < 2; ++t) {
        const int task = tid + t * NTH;
        const int row  = task >> 6;            // 0..TH-1
        const int l    = task & 63;            // 8-px chunk id
        const int xc   = l << 3;
        const int gy   = y0 + row;
        const unsigned char* smrow = sm + row * ROWB;

        // group bases + swizzle masks (halo group 64 has s=0, matching its
        // direct k layout)
        const int gA = (l == 0)  ? 64 : l - 1;
        const int gC = (l == 63) ? 64 : l + 1;
        const unsigned char* bA = smrow + gA * 128;
        const unsigned char* bB = smrow + l  * 128;
        const unsigned char* bC = smrow + gC * 128;
        const unsigned sA = (unsigned)((gA & 7) << 4);
        const unsigned sB = (unsigned)((l  & 7) << 4);
        const unsigned sC = (unsigned)((gC & 7) << 4);

        // hoist raw-content loads (overlap their latency with the FFMA2 stream)
        const float4 cA4 = *reinterpret_cast<const float4*>(cp + gy * WIDTH + xc);
        const float4 cB4 = *reinterpret_cast<const float4*>(cp + gy * WIDTH + xc + 4);

        u64 ac[8], as_[8];                     // packed accumulators per pixel
        #pragma unroll
        for (int o = 0; o < 8; ++o) { ac[o] = 0ull; as_[o] = 0ull; }

        #pragma unroll
        for (int j = 0; j < 14; ++j) {
            // window tuple j: group A (j<3, k=5+j), B (3<=j<11, k=j-3),
            // C (j>=11, k=j-11); byte = base + (16k ^ s)
            const unsigned char* p =
                (j < 3)  ? (bA + (((5 + j)  << 4) ^ sA)) :
                (j < 11) ? (bB + (((j - 3)  << 4) ^ sB)) :
                           (bC + (((j - 11) << 4) ^ sC));
            const ulonglong2 w = *reinterpret_cast<const ulonglong2*>(p);
            #pragma unroll
            for (int o = 0; o < 8; ++o) {
                const int k = j - o;
                if (k >= 0 && k < 7) {         // compile-time predicate
                    ac[o]  = fma2(G2[k], w.x, ac[o]);
                    as_[o] = fma2(G2[k], w.y, as_[o]);
                }
            }
        }

        const float craw[8] = {cA4.x, cA4.y, cA4.z, cA4.w,
                               cB4.x, cB4.y, cB4.z, cB4.w};

        float res[8];
        #pragma unroll
        for (int o = 0; o < 8; ++o) {
            float cm, cE2, smn, sE2;
            unpack2(ac[o],  cm,  cE2);
            unpack2(as_[o], smn, sE2);
            const float cv = fmaxf(fmaf(-cm,  cm,  cE2), 1e-6f);
            const float sv = fmaxf(fmaf(-smn, smn, sE2), 1e-6f);
            const float rqc = frsq_ap(cv);              // MUFU.RSQ (parallel)
            const float rqs = frsq_ap(sv);              // MUFU.RSQ (parallel)
            const float numer = fmaf(sv, rqs, 1e-5f);   // sqrt(sv) + eps
            const float dinv  = rqc - (1e-5f * rqc) * rqc; // ~1/(sqrt(cv)+eps)
            res[o] = fmaf(craw[o] - cm, numer * dinv, smn);
        }

        *reinterpret_cast<float4*>(op + gy * WIDTH + xc) =
            make_float4(res[0], res[1], res[2], res[3]);
        *reinterpret_cast<float4*>(op + gy * WIDTH + xc + 4) =
            make_float4(res[4], res[5], res[6], res[7]);
    }
}

extern "C" void kernel_launch(void* const* d_in, const int* in_sizes, int n_in,
                              void* d_out, int out_size) {
    const float* content = (const float*)d_in[0];
    const float* style   = (const float*)d_in[1];
    float*       out     = (float*)d_out;

    const int planes = in_sizes[0] / (WIDTH * HEIGHT);   // 4*64 = 256

    cudaFuncSetAttribute(adain_local_kernel,
                         cudaFuncAttributeMaxDynamicSharedMemorySize, SMEM_BYTES);

    dim3 grid(HEIGHT / TH, planes);
    adain_local_kernel<<<grid, NTH, SMEM_BYTES>>>(content, style, out);
}

// round 14
// speedup vs baseline: 1.2608x; 1.2608x over previous
#include <cuda_runtime.h>

#define WIDTH   512
#define HEIGHT  512
#define TH      8                  // output rows per CTA
#define NTH     256                // threads per CTA
#define ROWB    (WIDTH * 16)       // bytes per SMEM vb row (512 x 16B tuples)
#define SMEM_BYTES (TH * ROWB)     // 65536

typedef unsigned long long u64;

// reflect padding (pad=3 < dim, single reflection suffices)
__device__ __forceinline__ int refl(int i, int n) {
    i = i < 0 ? -i : i;
    return i >= n ? 2 * n - 2 - i : i;
}

// XOR swizzle: byte offset of tuple #x within a vb row.
__device__ __forceinline__ unsigned vboff(int x) {
    return (unsigned)((x ^ ((x >> 3) & 7)) << 4);
}

__device__ __forceinline__ u64 pack2(float lo, float hi) {
    u64 r; asm("mov.b64 %0, {%1, %2};" : "=l"(r) : "f"(lo), "f"(hi)); return r;
}
__device__ __forceinline__ void unpack2(u64 v, float& lo, float& hi) {
    asm("mov.b64 {%0, %1}, %2;" : "=f"(lo), "=f"(hi) : "l"(v));
}
// packed dual FMA -> FFMA2 in SASS (PTX-only form)
__device__ __forceinline__ u64 fma2(u64 a, u64 b, u64 c) {
    u64 d; asm("fma.rn.f32x2 %0, %1, %2, %3;" : "=l"(d) : "l"(a), "l"(b), "l"(c));
    return d;
}
__device__ __forceinline__ float frsq_ap(float x) {
    float r; asm("rsqrt.approx.f32 %0, %1;" : "=f"(r) : "f"(x)); return r;
}

// Stage-1 vertical blur for one column. EDGE=false: zero per-row address ALU
// (immediate-offset LDGs off two base pointers). EDGE=true: refl path.
template<bool EDGE>
__device__ __forceinline__ void stage1_col(const float* __restrict__ cp,
                                           const float* __restrict__ sp,
                                           unsigned char* sm,
                                           int x, int y0, const u64* G2) {
    const unsigned sb = vboff(x);
    u64 rc[7], rs[7];                          // ring: packed (v, v^2)
    const float* cr = cp + (y0 - 3) * WIDTH + x;   // valid base when !EDGE
    const float* sr = sp + (y0 - 3) * WIDTH + x;
    #pragma unroll
    for (int i = 0; i < TH + 6; ++i) {
        float c, s;
        if (EDGE) {
            const int gy = refl(y0 - 3 + i, HEIGHT);
            c = __ldg(cp + gy * WIDTH + x);
            s = __ldg(sp + gy * WIDTH + x);
        } else {
            c = __ldg(cr + i * WIDTH);         // LDG [R + imm]
            s = __ldg(sr + i * WIDTH);
        }
        rc[i % 7] = pack2(c, c * c);
        rs[i % 7] = pack2(s, s * s);
        if (i >= 6) {
            const int o = i - 6;               // output row within tile
            u64 a = 0ull, d = 0ull;            // (mean, E2) packed per tensor
            #pragma unroll
            for (int k = 0; k < 7; ++k) {
                const int q = (o + k) % 7;     // compile-time after unroll
                a = fma2(G2[k], rc[q], a);
                d = fma2(G2[k], rs[q], d);
            }
            ulonglong2 v; v.x = a; v.y = d;
            *reinterpret_cast<ulonglong2*>(sm + o * ROWB + sb) = v;
        }
    }
}

__global__ __launch_bounds__(NTH, 3)
void adain_local_kernel(const float* __restrict__ content,
                        const float* __restrict__ style,
                        float* __restrict__ out) {
    extern __shared__ unsigned char sm[];

    const float G[7] = {0.0044330481752437f, 0.0540055826224143f,
                        0.2420362293761143f, 0.3990502746173879f,
                        0.2420362293761143f, 0.0540055826224143f,
                        0.0044330481752437f};
    u64 G2[7];
    #pragma unroll
    for (int k = 0; k < 7; ++k) G2[k] = pack2(G[k], G[k]);

    const int plane = blockIdx.y;
    const int y0    = blockIdx.x * TH;
    const size_t pb = (size_t)plane * (WIDTH * HEIGHT);
    const float* cp = content + pb;
    const float* sp = style   + pb;
    float*       op = out     + pb;
    const int tid = threadIdx.x;

    // -------- Stage 1: vertical 7-tap blur; each thread handles 2 columns ---
    // 62/64 y-tiles take the zero-ALU interior path.
    if (y0 >= 3 && y0 + TH + 3 <= HEIGHT) {
        stage1_col<false>(cp, sp, sm, tid,       y0, G2);
        stage1_col<false>(cp, sp, sm, tid + NTH, y0, G2);
    } else {
        stage1_col<true >(cp, sp, sm, tid,       y0, G2);
        stage1_col<true >(cp, sp, sm, tid + NTH, y0, G2);
    }
    __syncthreads();

    // ---- Stage 2: horizontal 7-tap + AdaIN epilogue ------------------------
    // Task pairing: thread handles (row, l) and (row+4, SAME l) so the 14
    // refl+vboff window offsets are identical across both iterations (CSE),
    // and task-1 global addresses are task-0 base + immediate 4*WIDTH.
    {
        const int row  = tid >> 6;             // 0..3
        const int l    = tid & 63;             // 8-px chunk id (shared)
        const int xc   = l << 3;
        const unsigned char* smrow0 = sm + row * ROWB;
        const float* crawp = cp + (y0 + row) * WIDTH + xc;
        float*       outp  = op + (y0 + row) * WIDTH + xc;

        #pragma unroll
        for (int t = 0; t < 2; ++t) {
            const unsigned char* smrow = smrow0 + t * (4 * ROWB);
            const float* cbase = crawp + t * (4 * WIDTH);
            float*       obase = outp  + t * (4 * WIDTH);

            // hoist raw-content loads (overlap latency with the FFMA2 stream)
            const float4 cA = *reinterpret_cast<const float4*>(cbase);
            const float4 cB = *reinterpret_cast<const float4*>(cbase + 4);

            u64 ac[8], as_[8];                 // packed accumulators per pixel
            #pragma unroll
            for (int o = 0; o < 8; ++o) { ac[o] = 0ull; as_[o] = 0ull; }

            #pragma unroll
            for (int j = 0; j < 14; ++j) {
                const int xi = refl(xc - 3 + j, WIDTH);   // same both t (CSE)
                const ulonglong2 w =
                    *reinterpret_cast<const ulonglong2*>(smrow + vboff(xi));
                #pragma unroll
                for (int o = 0; o < 8; ++o) {
                    const int k = j - o;
                    if (k >= 0 && k < 7) {     // compile-time predicate
                        ac[o]  = fma2(G2[k], w.x, ac[o]);
                        as_[o] = fma2(G2[k], w.y, as_[o]);
                    }
                }
            }

            const float craw[8] = {cA.x, cA.y, cA.z, cA.w,
                                   cB.x, cB.y, cB.z, cB.w};

            float res[8];
            #pragma unroll
            for (int o = 0; o < 8; ++o) {
                float cm, cE2, smn, sE2;
                unpack2(ac[o],  cm,  cE2);
                unpack2(as_[o], smn, sE2);
                const float cv = fmaxf(fmaf(-cm,  cm,  cE2), 1e-6f);
                const float sv = fmaxf(fmaf(-smn, smn, sE2), 1e-6f);
                const float rqc = frsq_ap(cv);              // MUFU.RSQ
                const float rqs = frsq_ap(sv);              // MUFU.RSQ
                const float numer = fmaf(sv, rqs, 1e-5f);   // sqrt(sv) + eps
                const float dinv  = rqc - (1e-5f * rqc) * rqc;
                res[o] = fmaf(craw[o] - cm, numer * dinv, smn);
            }

            *reinterpret_cast<float4*>(obase) =
                make_float4(res[0], res[1], res[2], res[3]);
            *reinterpret_cast<float4*>(obase + 4) =
                make_float4(res[4], res[5], res[6], res[7]);
        }
    }
}

extern "C" void kernel_launch(void* const* d_in, const int* in_sizes, int n_in,
                              void* d_out, int out_size) {
    const float* content = (const float*)d_in[0];
    const float* style   = (const float*)d_in[1];
    float*       out     = (float*)d_out;

    const int planes = in_sizes[0] / (WIDTH * HEIGHT);   // 4*64 = 256

    cudaFuncSetAttribute(adain_local_kernel,
                         cudaFuncAttributeMaxDynamicSharedMemorySize, SMEM_BYTES);

    dim3 grid(HEIGHT / TH, planes);
    adain_local_kernel<<<grid, NTH, SMEM_BYTES>>>(content, style, out);
}